// round 17
// baseline (speedup 1.0000x reference)
#include <cuda_runtime.h>
#include <cuda_bf16.h>

#define BB 2
#define DD 10
#define HH 512
#define WW 512
#define HW (HH * WW)

__device__ __forceinline__ float4 fmax4(float4 a, float4 b) {
    return make_float4(fmaxf(a.x, b.x), fmaxf(a.y, b.y), fmaxf(a.z, b.z), fmaxf(a.w, b.w));
}

// component jj of quad
__device__ __forceinline__ float selB(float4 v, int jj) {
    float r = v.x;
    r = (jj == 1) ? v.y : r;
    r = (jj == 2) ? v.z : r;
    r = (jj == 3) ? v.w : r;
    return r;
}
// value at wq-1: component jj-1 for jj>=1, else edge scalar e
__device__ __forceinline__ float selA(float4 v, float e, int jj) {
    float r = e;
    r = (jj == 1) ? v.x : r;
    r = (jj == 2) ? v.y : r;
    r = (jj == 3) ? v.z : r;
    return r;
}
// value at wq+1: component jj+1 for jj<=2, else edge scalar e
__device__ __forceinline__ float selC(float4 v, float e, int jj) {
    float r = v.y;
    r = (jj == 1) ? v.z : r;
    r = (jj == 2) ? v.w : r;
    r = (jj == 3) ? e   : r;
    return r;
}

__global__ __launch_bounds__(128, 8)   // 64-reg cap, 8 CTAs/SM: finer barrier/overlap granularity
void quadinterp3d_kernel(const float* __restrict__ x, float* __restrict__ out) {
    // Block = 128 threads = one h-pair x 512 w. Each thread: 2 vertically-adjacent quads (8 voxels).
    __shared__ float4 sEw[128], sEx[128];   // edge exchange: {cm0,cm1,center_h,center_h1}
    __shared__ unsigned short q[512];       // (tid<<3 | k) codes; k = (hsel<<2)|jj
    __shared__ int qcnt;

    const int tid  = threadIdx.x;           // == w4
    const int lane = tid & 31;
    const int blk  = blockIdx.x;
    const int hpair = blk & 255;            // 0..255 per (b,d)
    const int t     = blk >> 8;             // 0..19 (B*D)
    const int d = t % DD;
    const int b = t / DD;
    const int h  = hpair << 1;              // even, 0..510 (covers h, h+1)
    const int w0 = tid << 2;

    if (tid == 0) qcnt = 0;

    const int off4 = (d * HH + h) * WW;
    const float* __restrict__ base = x + (size_t)b * DD * HW;
    const float* __restrict__ pc = base + off4 + w0;

    // Clamped row offsets relative to row h (replicate padding)
    const int dym   = (h > 0) ? WW : 0;                 // h-1
    const int rofs2 = WW + ((h < HH - 2) ? WW : 0);     // h+2 (clamped at top edge)
    const int dzm = (d > 0)      ? HW : 0;
    const int dzp = (d < DD - 1) ? HW : 0;

    // 12 independent LDG.128: planes (zm, d, zp) x rows (h-1, h, h+1, h+2)
    const float4 a0 = *reinterpret_cast<const float4*>(pc - dzm - dym);
    const float4 a1 = *reinterpret_cast<const float4*>(pc - dzm);
    const float4 a2 = *reinterpret_cast<const float4*>(pc - dzm + WW);
    const float4 a3 = *reinterpret_cast<const float4*>(pc - dzm + rofs2);
    const float4 b0 = *reinterpret_cast<const float4*>(pc - dym);
    const float4 b1 = *reinterpret_cast<const float4*>(pc);
    const float4 b2 = *reinterpret_cast<const float4*>(pc + WW);
    const float4 b3 = *reinterpret_cast<const float4*>(pc + rofs2);
    const float4 c0 = *reinterpret_cast<const float4*>(pc + dzp - dym);
    const float4 c1 = *reinterpret_cast<const float4*>(pc + dzp);
    const float4 c2 = *reinterpret_cast<const float4*>(pc + dzp + WW);
    const float4 c3 = *reinterpret_cast<const float4*>(pc + dzp + rofs2);

    // Shared partial maxima between the two rows' 26-neighbor trees
    const float4 B0 = fmax4(a1, c1);                   // non-center planes, row h
    const float4 B1 = fmax4(a2, c2);                   // non-center planes, row h+1
    const float4 A  = fmax4(fmax4(a0, c0), b0);        // all planes, row h-1
    const float4 C  = fmax4(fmax4(a3, c3), b3);        // all planes, row h+2
    const float4 cm0 = fmax4(fmax4(A, B0), fmax4(B1, b2));  // excl center (d,h)
    const float4 cm1 = fmax4(fmax4(B0, b1), fmax4(B1, C));  // excl center (d,h+1)

    // Block-level edge exchange (both rows + both centers, packed)
    sEw[tid] = make_float4(cm0.w, cm1.w, b1.w, b2.w);
    sEx[tid] = make_float4(cm0.x, cm1.x, b1.x, b2.x);
    __syncthreads();

    const bool atL = (tid == 0);
    const bool atR = (tid == 127);
    const float4 Lv = atL ? make_float4(cm0.x, cm1.x, b1.x, b2.x) : sEw[tid - 1];
    const float4 Rv = atR ? make_float4(cm0.w, cm1.w, b1.w, b2.w) : sEx[tid + 1];
    // Lv = {cm0L, cm1L, u0a, u0b},  Rv = {cm0R, cm1R, u5a, u5b}

    // ---- Row h mask ----
    const float w00 = fmaxf(fmaxf(Lv.x,  cm0.x), cm0.y);
    const float w01 = fmaxf(fmaxf(cm0.x, cm0.y), cm0.z);
    const float w02 = fmaxf(fmaxf(cm0.y, cm0.z), cm0.w);
    const float w03 = fmaxf(fmaxf(cm0.z, cm0.w), Rv.x);
    const float n00 = fmaxf(fmaxf(w00, fmaxf(Lv.z, b1.y)), 0.0f);
    const float n01 = fmaxf(fmaxf(w01, fmaxf(b1.x, b1.z)), 0.0f);
    const float n02 = fmaxf(fmaxf(w02, fmaxf(b1.y, b1.w)), 0.0f);
    const float n03 = fmaxf(fmaxf(w03, fmaxf(b1.z, Rv.z)), 0.0f);
    const bool m00 = b1.x > n00, m01 = b1.y > n01, m02 = b1.z > n02, m03 = b1.w > n03;

    // ---- Row h+1 mask ----
    const float w10 = fmaxf(fmaxf(Lv.y,  cm1.x), cm1.y);
    const float w11 = fmaxf(fmaxf(cm1.x, cm1.y), cm1.z);
    const float w12 = fmaxf(fmaxf(cm1.y, cm1.z), cm1.w);
    const float w13 = fmaxf(fmaxf(cm1.z, cm1.w), Rv.y);
    const float n10 = fmaxf(fmaxf(w10, fmaxf(Lv.w, b2.y)), 0.0f);
    const float n11 = fmaxf(fmaxf(w11, fmaxf(b2.x, b2.z)), 0.0f);
    const float n12 = fmaxf(fmaxf(w12, fmaxf(b2.y, b2.w)), 0.0f);
    const float n13 = fmaxf(fmaxf(w13, fmaxf(b2.z, Rv.w)), 0.0f);
    const bool m10 = b2.x > n10, m11 = b2.y > n11, m12 = b2.z > n12, m13 = b2.w > n13;

    // ---- Default stores FIRST (coords = grid, y = x); queue overwrites maxima. ----
    const size_t plsz = (size_t)DD * HW;
    const size_t in0 = (size_t)off4 + w0;
    const size_t in1 = in0 + WW;
    const float fd = (float)d, fh = (float)h, fw = (float)w0;
    float* const o0 = out + (size_t)(b * 3 + 0) * plsz;
    float* const o1 = out + (size_t)(b * 3 + 1) * plsz;
    float* const o2 = out + (size_t)(b * 3 + 2) * plsz;
    float* const oy = out + (size_t)BB * 3 * plsz + (size_t)b * plsz;
    *reinterpret_cast<float4*>(o0 + in0) = make_float4(fd, fd, fd, fd);
    *reinterpret_cast<float4*>(o0 + in1) = make_float4(fd, fd, fd, fd);
    *reinterpret_cast<float4*>(o1 + in0) = make_float4(fh, fh, fh, fh);
    *reinterpret_cast<float4*>(o1 + in1) = make_float4(fh + 1.0f, fh + 1.0f, fh + 1.0f, fh + 1.0f);
    *reinterpret_cast<float4*>(o2 + in0) = make_float4(fw, fw + 1.0f, fw + 2.0f, fw + 3.0f);
    *reinterpret_cast<float4*>(o2 + in1) = make_float4(fw, fw + 1.0f, fw + 2.0f, fw + 3.0f);
    *reinterpret_cast<float4*>(oy + in0) = b1;
    *reinterpret_cast<float4*>(oy + in1) = b2;

    // ---- Warp-aggregated queue push (8 ballots, one shared atomic per warp) ----
    const unsigned bl[8] = {
        __ballot_sync(0xffffffffu, m00), __ballot_sync(0xffffffffu, m01),
        __ballot_sync(0xffffffffu, m02), __ballot_sync(0xffffffffu, m03),
        __ballot_sync(0xffffffffu, m10), __ballot_sync(0xffffffffu, m11),
        __ballot_sync(0xffffffffu, m12), __ballot_sync(0xffffffffu, m13)
    };
    const bool mk[8] = {m00, m01, m02, m03, m10, m11, m12, m13};
    int nWarp = 0;
    #pragma unroll
    for (int k = 0; k < 8; k++) nWarp += __popc(bl[k]);
    int basei = 0;
    if (lane == 0 && nWarp) basei = atomicAdd(&qcnt, nWarp);
    basei = __shfl_sync(0xffffffffu, basei, 0);
    {
        const unsigned lm = (1u << lane) - 1u;
        int p = 0;
        #pragma unroll
        for (int k = 0; k < 8; k++) {
            if (mk[k]) q[basei + p + __popc(bl[k] & lm)] = (unsigned short)((tid << 3) | k);
            p += __popc(bl[k]);
        }
    }
    __syncthreads();

    // ---- Dense queue processing (one thread per maximum), vectorized gather ----
    const int cnt = qcnt;
    for (int i = tid; i < cnt; i += 128) {
        const int code = q[i];
        const int jj   = code & 3;
        const int hq   = h + ((code >> 2) & 1);
        const int wq   = (((code >> 3) << 2) | jj);
        const int wb   = wq & ~3;

        const float* __restrict__ rowc = base + (d * HH + hq) * WW;
        const int qym = (hq > 0)      ? WW : 0;
        const int qyp = (hq < HH - 1) ? WW : 0;

        const float4 Q4 = *reinterpret_cast<const float4*>(rowc + wb);
        const float4 Q3 = *reinterpret_cast<const float4*>(rowc - qym + wb);
        const float4 Q5 = *reinterpret_cast<const float4*>(rowc + qyp + wb);
        const float4 Q1 = *reinterpret_cast<const float4*>(rowc - dzm + wb);
        const float4 Q7 = *reinterpret_cast<const float4*>(rowc + dzp + wb);

        const float e0 = __ldg(rowc - dzm - qym + wq);
        const float e2 = __ldg(rowc - dzm + qyp + wq);
        const float e6 = __ldg(rowc + dzp - qym + wq);
        const float e8 = __ldg(rowc + dzp + qyp + wq);

        const bool eLz = (jj == 0), eRz = (jj == 3);
        float x4 = 0.f, x3 = 0.f, x5 = 0.f, x1 = 0.f, x7 = 0.f;
        if (eLz | eRz) {
            const int we = eLz ? (wq + ((wq > 0) ? -1 : 0))
                               : (wq + ((wq < WW - 1) ? 1 : 0));
            x4 = __ldg(rowc + we);
            x3 = __ldg(rowc - qym + we);
            x5 = __ldg(rowc + qyp + we);
            x1 = __ldg(rowc - dzm + we);
            x7 = __ldg(rowc + dzp + we);
        }

        const float cc = selB(Q4, jj), a4 = selA(Q4, x4, jj), c4 = selC(Q4, x4, jj);
        const float b3v = selB(Q3, jj), a3v = selA(Q3, x3, jj), c3v = selC(Q3, x3, jj);
        const float b5v = selB(Q5, jj), a5v = selA(Q5, x5, jj), c5v = selC(Q5, x5, jj);
        const float b1v = selB(Q1, jj), a1v = selA(Q1, x1, jj), c1v = selC(Q1, x1, jj);
        const float b7v = selB(Q7, jj), a7v = selA(Q7, x7, jj), c7v = selC(Q7, x7, jj);

        // Newton solve (same algebra as the verified kernels; H symmetric)
        const float gx = 0.5f * (c4 - a4);
        const float gy = 0.5f * (b5v - b3v);
        const float gs = 0.5f * (b7v - b1v);

        const float h00 = a4 + c4 - 2.0f * cc;
        const float h11 = b3v + b5v - 2.0f * cc;
        const float h22 = b1v + b7v - 2.0f * cc;
        const float h01 = 0.25f * (a3v + c5v - a5v - c3v);
        const float h12 = 0.25f * (e0 + e8 - e6 - e2);
        const float h02 = 0.25f * (a1v + c7v - a7v - c1v);

        const float c00 = h11 * h22 - h12 * h12;
        const float c01 = h01 * h22 - h12 * h02;
        const float c02 = h01 * h12 - h11 * h02;
        const float det = h00 * c00 - h01 * c01 + h02 * c02;

        const float t1 = gy * h22 - h12 * gs;
        const float t2 = gy * h12 - h11 * gs;
        const float t3 = h01 * gs - gy * h02;

        const float inv = 1.0f / det;
        const float sx = (gx * c00 - h01 * t1 + h02 * t2) * inv;
        const float sy = (h00 * t1 - gx * c01 + h02 * t3) * inv;
        const float ss = (h00 * (h11 * gs - h12 * gy) - h01 * t3 + gx * c02) * inv;

        float d0 = -sx, d1 = -sy, d2 = -ss;
        const float far = fmaxf(fmaxf(fabsf(d0), fabsf(d1)), fabsf(d2));
        if (far > 0.7f) { d0 = 0.0f; d1 = 0.0f; d2 = 0.0f; }

        const float ry = cc + 0.5f * (gx * d0 + gy * d1 + gs * d2) + 10.0f;

        const size_t innq = (size_t)(d * HH + hq) * WW + wq;
        o0[innq] = (float)d  + d2;
        o1[innq] = (float)hq + d1;
        o2[innq] = (float)wq + d0;
        oy[innq] = ry;
    }
}

extern "C" void kernel_launch(void* const* d_in, const int* in_sizes, int n_in,
                              void* d_out, int out_size) {
    const float* x = (const float*)d_in[0];
    float* out = (float*)d_out;
    const int grid = BB * DD * (HH / 2);   // 5,120 blocks of 128 threads
    quadinterp3d_kernel<<<grid, 128>>>(x, out);
}